// round 2
// baseline (speedup 1.0000x reference)
#include <cuda_runtime.h>
#include <math.h>

#define B_   2
#define T_   2048
#define E_   2048
#define H_   16
#define M_   4
#define HD_  32
#define KVW_ 512
#define NR_  (B_*T_)   // 4096 rows

// ---------------- scratch (static device globals; no allocation) ----------------
__device__ __align__(16) float g_q[(size_t)NR_ * E_];    // 33.5 MB
__device__ __align__(16) float g_k[(size_t)NR_ * KVW_];  // 8.4 MB
__device__ __align__(16) float g_v[(size_t)NR_ * KVW_];  // 8.4 MB
__device__ __align__(16) float g_n[(size_t)NR_ * E_];    // 33.5 MB

// ---------------- generic fp32 SGEMM: C[N,J] = A[N,K] @ W[J,K]^T ----------------
// 128x128 block tile, BK=8, 256 threads, 8x8 per-thread microtile.
__global__ __launch_bounds__(256) void sgemm_nt(
    const float* __restrict__ A, const float* __restrict__ W,
    float* __restrict__ C, int N, int J, int K)
{
    __shared__ float As[8][128];
    __shared__ float Bs[8][128];
    const int tid  = threadIdx.x;
    const int bm   = blockIdx.y * 128;
    const int bn   = blockIdx.x * 128;
    const int lrow = tid >> 1;
    const int lseg = (tid & 1) << 2;
    const int tx   = tid & 15;
    const int ty   = tid >> 4;

    const float* Ap = A + (size_t)(bm + lrow) * K + lseg;
    const float* Wp = W + (size_t)(bn + lrow) * K + lseg;

    float acc[8][8];
#pragma unroll
    for (int i = 0; i < 8; i++)
#pragma unroll
        for (int j = 0; j < 8; j++) acc[i][j] = 0.f;

#pragma unroll 1
    for (int k0 = 0; k0 < K; k0 += 8) {
        float4 a4 = *(const float4*)(Ap + k0);
        float4 b4 = *(const float4*)(Wp + k0);
        __syncthreads();
        As[lseg+0][lrow] = a4.x; As[lseg+1][lrow] = a4.y;
        As[lseg+2][lrow] = a4.z; As[lseg+3][lrow] = a4.w;
        Bs[lseg+0][lrow] = b4.x; Bs[lseg+1][lrow] = b4.y;
        Bs[lseg+2][lrow] = b4.z; Bs[lseg+3][lrow] = b4.w;
        __syncthreads();
#pragma unroll
        for (int kk = 0; kk < 8; kk++) {
            float4 a0 = *(const float4*)&As[kk][ty*4];
            float4 a1 = *(const float4*)&As[kk][64 + ty*4];
            float4 b0 = *(const float4*)&Bs[kk][tx*4];
            float4 b1 = *(const float4*)&Bs[kk][64 + tx*4];
            float a[8] = {a0.x,a0.y,a0.z,a0.w,a1.x,a1.y,a1.z,a1.w};
            float b[8] = {b0.x,b0.y,b0.z,b0.w,b1.x,b1.y,b1.z,b1.w};
#pragma unroll
            for (int i = 0; i < 8; i++)
#pragma unroll
                for (int j = 0; j < 8; j++) acc[i][j] += a[i]*b[j];
        }
    }
#pragma unroll
    for (int i = 0; i < 8; i++) {
        int r = bm + ((i < 4) ? (ty*4 + i) : (64 + ty*4 + i - 4));
        float4 o0 = make_float4(acc[i][0],acc[i][1],acc[i][2],acc[i][3]);
        float4 o1 = make_float4(acc[i][4],acc[i][5],acc[i][6],acc[i][7]);
        *(float4*)&C[(size_t)r*J + bn + tx*4]      = o0;
        *(float4*)&C[(size_t)r*J + bn + 64 + tx*4] = o1;
    }
}

// ---------------- interleaved RoPE, in place ----------------
// buf: (B*T, nh, 32); cos/sin: (T, 16)
__global__ void rope_kernel(float* __restrict__ buf,
                            const float* __restrict__ cosb,
                            const float* __restrict__ sinb, int nh)
{
    int idx = blockIdx.x * blockDim.x + threadIdx.x;
    int total = NR_ * nh * 16;
    if (idx >= total) return;
    int j    = idx & 15;
    int rest = idx >> 4;
    int head = rest % nh;
    int row  = rest / nh;
    int t    = row & (T_ - 1);
    float c = cosb[t*16 + j];
    float s = sinb[t*16 + j];
    float* p = buf + (size_t)row * (nh*32) + head*32 + 2*j;
    float x1 = p[0], x2 = p[1];
    p[0] = x1*c - x2*s;
    p[1] = x1*s + x2*c;
}

// ---------------- flash attention (4-member ensemble) + weighted combine + RMS norm ----------------
// grid: (T/64, H, B). block: 256. One block owns a 64-row q tile for one (b,h).
// Members processed sequentially with online softmax; combined += w_m * O_m / l_m.
// Epilogue: RMS-norm over 128 value dims * gamma, written to g_n (B,T, h*128+e).
__global__ __launch_bounds__(256) void attn_kernel(
    const float* __restrict__ q, const float* __restrict__ k, const float* __restrict__ v,
    const float* __restrict__ rawm, const float* __restrict__ wsc,
    const float* __restrict__ gamma, float* __restrict__ outn)
{
    extern __shared__ float smf[];
    float* Qs   = smf;             // 64*33
    float* Ks   = Qs + 64*33;      // 64*33
    float* Vs   = Ks + 64*33;      // 64*128 (16B aligned: offset 4224 floats)
    float* Ps   = Vs + 64*128;     // 64*65
    float* m_s  = Ps + 64*65;      // 64
    float* l_s  = m_s + 64;        // 64
    float* al_s = l_s + 64;        // 64
    float* gma  = al_s + 64;       // 128

    const int tid  = threadIdx.x;
    const int tx   = tid & 15;
    const int ty   = tid >> 4;
    const int lane = tid & 31;
    const int warp = tid >> 5;
    const int qt   = (int)gridDim.x - 1 - (int)blockIdx.x;  // heavy tiles first
    const int h    = blockIdx.y;
    const int b    = blockIdx.z;
    const int hkv  = h >> 2;
    const float scale = 0.17677669529663687f;  // 32^-0.5

    if (tid < 128) gma[tid] = gamma[tid];
    const float ws0 = wsc[0];

    float comb[4][8];
#pragma unroll
    for (int i = 0; i < 4; i++)
#pragma unroll
        for (int j = 0; j < 8; j++) comb[i][j] = 0.f;

    const int rowbase = b*T_ + qt*64;

    for (int mm = 0; mm < 4; mm++) {
        __syncthreads();  // protect l_s / smem reuse across members
        if (tid < 64) { m_s[tid] = -1e30f; l_s[tid] = 0.f; }
        // load Q tile (64x32) for this member, padded stride 33
        {
#pragma unroll
            for (int u = 0; u < 2; u++) {
                int li = tid*2 + u;
                int r = li >> 3, seg = li & 7;
                const float* p = q + (size_t)(rowbase + r)*E_ + (h*4 + mm)*32 + seg*4;
                float4 qa = *(const float4*)p;
                float* d = Qs + r*33 + seg*4;
                d[0]=qa.x; d[1]=qa.y; d[2]=qa.z; d[3]=qa.w;
            }
        }
        float acc[4][8];
#pragma unroll
        for (int i = 0; i < 4; i++)
#pragma unroll
            for (int j = 0; j < 8; j++) acc[i][j] = 0.f;

#pragma unroll 1
        for (int kt = 0; kt <= qt; kt++) {
            const int kbase = b*T_ + kt*64;
            // stage K (64x32) and V (64x128) via registers
            float4 kr[2], vr[8];
#pragma unroll
            for (int u = 0; u < 2; u++) {
                int li = tid*2 + u;
                int r = li >> 3, seg = li & 7;
                kr[u] = *(const float4*)(k + (size_t)(kbase + r)*KVW_ + (hkv*4 + mm)*32 + seg*4);
            }
#pragma unroll
            for (int u = 0; u < 8; u++) {
                int li = u*256 + tid;
                int r = li >> 5, f4 = li & 31;
                vr[u] = *(const float4*)(v + (size_t)(kbase + r)*KVW_ + hkv*128 + f4*4);
            }
            __syncthreads();   // previous tile's smem reads complete
#pragma unroll
            for (int u = 0; u < 2; u++) {
                int li = tid*2 + u;
                int r = li >> 3, seg = li & 7;
                float* d = Ks + r*33 + seg*4;
                d[0]=kr[u].x; d[1]=kr[u].y; d[2]=kr[u].z; d[3]=kr[u].w;
            }
#pragma unroll
            for (int u = 0; u < 8; u++) {
                int li = u*256 + tid;
                *(float4*)(Vs + li*4) = vr[u];
            }
            __syncthreads();

            // S = scale * Q K^T (64x64), microtile 4x4: rows ty+16i, cols tx+16j
            float s[4][4];
#pragma unroll
            for (int i = 0; i < 4; i++)
#pragma unroll
                for (int j = 0; j < 4; j++) s[i][j] = 0.f;
#pragma unroll 8
            for (int d = 0; d < 32; d++) {
                float a[4], bb[4];
#pragma unroll
                for (int i = 0; i < 4; i++) a[i]  = Qs[(ty + 16*i)*33 + d];
#pragma unroll
                for (int j = 0; j < 4; j++) bb[j] = Ks[(tx + 16*j)*33 + d];
#pragma unroll
                for (int i = 0; i < 4; i++)
#pragma unroll
                    for (int j = 0; j < 4; j++) s[i][j] += a[i]*bb[j];
            }
#pragma unroll
            for (int i = 0; i < 4; i++) {
                int qi = qt*64 + ty + 16*i;
#pragma unroll
                for (int j = 0; j < 4; j++) {
                    int kj = kt*64 + tx + 16*j;
                    float sv = s[i][j]*scale;
                    if (kj > qi) sv = -1e30f;
                    s[i][j] = sv;
                    Ps[(ty + 16*i)*65 + tx + 16*j] = sv;
                }
            }
            __syncthreads();

            // row max -> new m, alpha (8 warps x 8 rows)
#pragma unroll
            for (int q8 = 0; q8 < 8; q8++) {
                int r = warp*8 + q8;
                float vmax = fmaxf(Ps[r*65 + lane], Ps[r*65 + lane + 32]);
#pragma unroll
                for (int o = 16; o > 0; o >>= 1)
                    vmax = fmaxf(vmax, __shfl_xor_sync(0xffffffffu, vmax, o));
                if (lane == 0) {
                    float nm = fmaxf(m_s[r], vmax);
                    al_s[r] = __expf(m_s[r] - nm);
                    m_s[r] = nm;
                }
            }
            __syncthreads();

            // p = exp(s - m); rescale O by alpha
#pragma unroll
            for (int i = 0; i < 4; i++) {
                int r = ty + 16*i;
                float mv = m_s[r], al = al_s[r];
#pragma unroll
                for (int j = 0; j < 4; j++)
                    Ps[r*65 + tx + 16*j] = __expf(s[i][j] - mv);
#pragma unroll
                for (int j = 0; j < 8; j++) acc[i][j] *= al;
            }
            __syncthreads();

            // row sum -> l (concurrent with PV is safe: disjoint writes)
#pragma unroll
            for (int q8 = 0; q8 < 8; q8++) {
                int r = warp*8 + q8;
                float vs = Ps[r*65 + lane] + Ps[r*65 + lane + 32];
#pragma unroll
                for (int o = 16; o > 0; o >>= 1)
                    vs += __shfl_xor_sync(0xffffffffu, vs, o);
                if (lane == 0) l_s[r] = l_s[r]*al_s[r] + vs;
            }

            // O += P V : microtile 4 rows x 8 cols (cols tx*4..+3 and 64+tx*4..+3)
#pragma unroll 4
            for (int kk = 0; kk < 64; kk++) {
                float pp[4];
#pragma unroll
                for (int i = 0; i < 4; i++) pp[i] = Ps[(ty + 16*i)*65 + kk];
                float4 v0 = *(const float4*)(Vs + kk*128 + tx*4);
                float4 v1 = *(const float4*)(Vs + kk*128 + 64 + tx*4);
                float vv[8] = {v0.x,v0.y,v0.z,v0.w,v1.x,v1.y,v1.z,v1.w};
#pragma unroll
                for (int i = 0; i < 4; i++)
#pragma unroll
                    for (int j = 0; j < 8; j++) acc[i][j] += pp[i]*vv[j];
            }
        } // kt

        __syncthreads();  // l_s final
        float wm = tanhf(rawm[mm]) * ws0;
#pragma unroll
        for (int i = 0; i < 4; i++) {
            float inv = wm / l_s[ty + 16*i];
#pragma unroll
            for (int j = 0; j < 8; j++) comb[i][j] += inv * acc[i][j];
        }
    } // member

    // RMS norm over 128 dims (+gamma), write to outn
#pragma unroll
    for (int i = 0; i < 4; i++) {
        float ps = 0.f;
#pragma unroll
        for (int j = 0; j < 8; j++) ps += comb[i][j]*comb[i][j];
        Ps[(ty + 16*i)*65 + tx] = ps;
    }
    __syncthreads();
    if (tid < 64) {
        float ssum = 0.f;
#pragma unroll
        for (int xx = 0; xx < 16; xx++) ssum += Ps[tid*65 + xx];
        m_s[tid] = rsqrtf(ssum*(1.0f/128.0f) + 1e-5f);
    }
    __syncthreads();
#pragma unroll
    for (int i = 0; i < 4; i++) {
        int r = ty + 16*i;
        float rs = m_s[r];
        float* op = outn + (size_t)(rowbase + r)*E_ + h*128;
        float4 o0, o1;
        o0.x = comb[i][0]*rs*gma[tx*4+0];
        o0.y = comb[i][1]*rs*gma[tx*4+1];
        o0.z = comb[i][2]*rs*gma[tx*4+2];
        o0.w = comb[i][3]*rs*gma[tx*4+3];
        o1.x = comb[i][4]*rs*gma[64+tx*4+0];
        o1.y = comb[i][5]*rs*gma[64+tx*4+1];
        o1.z = comb[i][6]*rs*gma[64+tx*4+2];
        o1.w = comb[i][7]*rs*gma[64+tx*4+3];
        *(float4*)(op + tx*4)      = o0;
        *(float4*)(op + 64 + tx*4) = o1;
    }
}

// ---------------- launch ----------------
extern "C" void kernel_launch(void* const* d_in, const int* in_sizes, int n_in,
                              void* d_out, int out_size)
{
    const float* x     = (const float*)d_in[0];
    const float* cosb  = (const float*)d_in[1];
    const float* sinb  = (const float*)d_in[2];
    const float* q_w   = (const float*)d_in[3];
    const float* k_w   = (const float*)d_in[4];
    const float* v_w   = (const float*)d_in[5];
    const float* out_w = (const float*)d_in[6];
    const float* rawm  = (const float*)d_in[7];
    const float* wsc   = (const float*)d_in[8];
    const float* gamma = (const float*)d_in[9];
    float* out = (float*)d_out;

    float *gq, *gk, *gv, *gn;
    cudaGetSymbolAddress((void**)&gq, g_q);
    cudaGetSymbolAddress((void**)&gk, g_k);
    cudaGetSymbolAddress((void**)&gv, g_v);
    cudaGetSymbolAddress((void**)&gn, g_n);

    const int smem_bytes = (64*33*2 + 64*128 + 64*65 + 64*3 + 128) * sizeof(float); // 67584
    cudaFuncSetAttribute(attn_kernel, cudaFuncAttributeMaxDynamicSharedMemorySize, smem_bytes);

    dim3 thr(256);
    // projections
    sgemm_nt<<<dim3(E_/128,  NR_/128), thr>>>(x, q_w, gq, NR_, E_,   E_);
    sgemm_nt<<<dim3(KVW_/128, NR_/128), thr>>>(x, k_w, gk, NR_, KVW_, E_);
    sgemm_nt<<<dim3(KVW_/128, NR_/128), thr>>>(x, v_w, gv, NR_, KVW_, E_);
    // RoPE (q: 64 heads, k: 16 heads)
    rope_kernel<<<(NR_*64*16)/256, 256>>>(gq, cosb, sinb, 64);
    rope_kernel<<<(NR_*16*16)/256, 256>>>(gk, cosb, sinb, 16);
    // attention + combine + RMS norm
    attn_kernel<<<dim3(T_/64, H_, B_), thr, smem_bytes>>>(gq, gk, gv, rawm, wsc, gamma, gn);
    // output projection
    sgemm_nt<<<dim3(E_/128, NR_/128), thr>>>(gn, out_w, out, NR_, E_, E_);
}

// round 4
// speedup vs baseline: 1.2746x; 1.2746x over previous
#include <cuda_runtime.h>
#include <cuda_bf16.h>
#include <math.h>
#include <stdint.h>

#define B_   2
#define T_   2048
#define E_   2048
#define H_   16
#define KVW_ 512
#define NR_  (B_*T_)   // 4096 rows

// ---------------- scratch (static device globals; no allocation) ----------------
__device__ __align__(16) float g_q[(size_t)NR_ * E_];
__device__ __align__(16) float g_k[(size_t)NR_ * KVW_];
__device__ __align__(16) float g_v[(size_t)NR_ * KVW_];
__device__ __align__(16) float g_n[(size_t)NR_ * E_];
// bf16 split buffers
__device__ __align__(16) __nv_bfloat16 g_ah[(size_t)NR_ * E_];   // x, later normed
__device__ __align__(16) __nv_bfloat16 g_al[(size_t)NR_ * E_];
__device__ __align__(16) __nv_bfloat16 g_qwh[(size_t)E_ * E_];
__device__ __align__(16) __nv_bfloat16 g_qwl[(size_t)E_ * E_];
__device__ __align__(16) __nv_bfloat16 g_kwh[(size_t)KVW_ * E_];
__device__ __align__(16) __nv_bfloat16 g_kwl[(size_t)KVW_ * E_];
__device__ __align__(16) __nv_bfloat16 g_vwh[(size_t)KVW_ * E_];
__device__ __align__(16) __nv_bfloat16 g_vwl[(size_t)KVW_ * E_];
__device__ __align__(16) __nv_bfloat16 g_owh[(size_t)E_ * E_];
__device__ __align__(16) __nv_bfloat16 g_owl[(size_t)E_ * E_];

__device__ __forceinline__ uint32_t smem_u32(const void* p) {
    uint32_t a;
    asm("{ .reg .u64 t; cvta.to.shared.u64 t, %1; cvt.u32.u64 %0, t; }" : "=r"(a) : "l"(p));
    return a;
}
__device__ __forceinline__ void ldsm_x4(uint32_t* r, uint32_t addr) {
    asm volatile("ldmatrix.sync.aligned.m8n8.x4.shared.b16 {%0,%1,%2,%3}, [%4];"
        : "=r"(r[0]), "=r"(r[1]), "=r"(r[2]), "=r"(r[3]) : "r"(addr));
}
__device__ __forceinline__ void ldsm_x2(uint32_t* r, uint32_t addr) {
    asm volatile("ldmatrix.sync.aligned.m8n8.x2.shared.b16 {%0,%1}, [%2];"
        : "=r"(r[0]), "=r"(r[1]) : "r"(addr));
}
__device__ __forceinline__ void mma_bf16(float* d, const uint32_t* a, const uint32_t* b) {
    asm volatile("mma.sync.aligned.m16n8k16.row.col.f32.bf16.bf16.f32 "
        "{%0,%1,%2,%3}, {%4,%5,%6,%7}, {%8,%9}, {%0,%1,%2,%3};"
        : "+f"(d[0]), "+f"(d[1]), "+f"(d[2]), "+f"(d[3])
        : "r"(a[0]), "r"(a[1]), "r"(a[2]), "r"(a[3]), "r"(b[0]), "r"(b[1]));
}

// ---------------- fp32 -> (bf16 hi, bf16 lo) split ----------------
__global__ void cvt_split(const float4* __restrict__ in,
                          __nv_bfloat162* __restrict__ hi,
                          __nv_bfloat162* __restrict__ lo, int n4)
{
    int i = blockIdx.x * blockDim.x + threadIdx.x;
    if (i >= n4) return;
    float4 v = in[i];
    __nv_bfloat16 h0 = __float2bfloat16(v.x), h1 = __float2bfloat16(v.y);
    __nv_bfloat16 h2 = __float2bfloat16(v.z), h3 = __float2bfloat16(v.w);
    __nv_bfloat16 l0 = __float2bfloat16(v.x - __bfloat162float(h0));
    __nv_bfloat16 l1 = __float2bfloat16(v.y - __bfloat162float(h1));
    __nv_bfloat16 l2 = __float2bfloat16(v.z - __bfloat162float(h2));
    __nv_bfloat16 l3 = __float2bfloat16(v.w - __bfloat162float(h3));
    hi[i*2]   = __halves2bfloat162(h0, h1);
    hi[i*2+1] = __halves2bfloat162(h2, h3);
    lo[i*2]   = __halves2bfloat162(l0, l1);
    lo[i*2+1] = __halves2bfloat162(l2, l3);
}

// ---------------- HMMA GEMM: C[N,J] = A[N,K] @ W[J,K]^T, split-bf16 x3 ----------------
// 128x128 tile/CTA, BK=32, 256 threads (8 warps, each 64x32).
// smem tiles padded to stride 40 bf16 (80B) -> conflict-free ldmatrix rounds.
#define TSTRIDE 40
__global__ __launch_bounds__(256) void mma_gemm(
    const __nv_bfloat16* __restrict__ Ah, const __nv_bfloat16* __restrict__ Al,
    const __nv_bfloat16* __restrict__ Bh, const __nv_bfloat16* __restrict__ Bl,
    float* __restrict__ C, int J, int K)
{
    __shared__ __align__(16) __nv_bfloat16 sm[4][128 * TSTRIDE];  // AH, AL, BH, BL

    const int tid  = threadIdx.x;
    const int lane = tid & 31;
    const int warp = tid >> 5;
    const int wr   = warp >> 2;   // 0..1 : 64-row strip
    const int wc   = warp & 3;    // 0..3 : 32-col strip
    const int bm   = blockIdx.y * 128;
    const int bn   = blockIdx.x * 128;

    const uint32_t sA_h = smem_u32(sm[0]);
    const uint32_t sA_l = smem_u32(sm[1]);
    const uint32_t sB_h = smem_u32(sm[2]);
    const uint32_t sB_l = smem_u32(sm[3]);

    const int K16 = K >> 4;  // row stride in uint4 (8 bf16) units... actually K/8
    const int K8 = K >> 3;
    const uint4* pAh = (const uint4*)Ah;
    const uint4* pAl = (const uint4*)Al;
    const uint4* pBh = (const uint4*)Bh;
    const uint4* pBl = (const uint4*)Bl;
    (void)K16;

    float d[4][4][4];
#pragma unroll
    for (int mi = 0; mi < 4; mi++)
#pragma unroll
        for (int ni = 0; ni < 4; ni++)
#pragma unroll
            for (int e = 0; e < 4; e++) d[mi][ni][e] = 0.f;

    // ldmatrix per-thread addresses (byte offsets into a tile)
    // A x4: row = mbase + (lane&15), col(bf16) = kk + (lane>>4)*8
    // B x2: row = nbase + (lane&7),  col(bf16) = kk + ((lane>>3)&1)*8
    const int a_row = lane & 15, a_coff = (lane >> 4) * 8;
    const int b_row = lane & 7,  b_coff = ((lane >> 3) & 1) * 8;

    const int nit = K >> 5;
#pragma unroll 1
    for (int it = 0; it < nit; it++) {
        const int k0u4 = it * 4;   // k offset in uint4 units (32 bf16 = 4 uint4)
        __syncthreads();
        // load 4 tiles of 128x32 bf16; each thread: 2 chunks (16B) per tile
#pragma unroll
        for (int u = 0; u < 2; u++) {
            int c   = u * 256 + tid;       // 0..511
            int row = c >> 2, ch = c & 3;
            size_t ga = (size_t)(bm + row) * K8 + k0u4 + ch;
            size_t gb = (size_t)(bn + row) * K8 + k0u4 + ch;
            uint4* dsta = (uint4*)((char*)sm[0] + row * (TSTRIDE*2) + ch * 16);
            uint4* dstb = (uint4*)((char*)sm[1] + row * (TSTRIDE*2) + ch * 16);
            uint4* dstc = (uint4*)((char*)sm[2] + row * (TSTRIDE*2) + ch * 16);
            uint4* dstd = (uint4*)((char*)sm[3] + row * (TSTRIDE*2) + ch * 16);
            *dsta = pAh[ga];
            *dstb = pAl[ga];
            *dstc = pBh[gb];
            *dstd = pBl[gb];
        }
        __syncthreads();

#pragma unroll
        for (int kk = 0; kk < 32; kk += 16) {
            uint32_t ah[4][4], al[4][4], bh[4][2], bl[4][2];
#pragma unroll
            for (int mi = 0; mi < 4; mi++) {
                int row = wr*64 + mi*16 + a_row;
                uint32_t off = (uint32_t)(row * (TSTRIDE*2) + (kk + a_coff) * 2);
                ldsm_x4(ah[mi], sA_h + off);
                ldsm_x4(al[mi], sA_l + off);
            }
#pragma unroll
            for (int ni = 0; ni < 4; ni++) {
                int row = wc*32 + ni*8 + b_row;
                uint32_t off = (uint32_t)(row * (TSTRIDE*2) + (kk + b_coff) * 2);
                ldsm_x2(bh[ni], sB_h + off);
                ldsm_x2(bl[ni], sB_l + off);
            }
#pragma unroll
            for (int mi = 0; mi < 4; mi++)
#pragma unroll
                for (int ni = 0; ni < 4; ni++) {
                    mma_bf16(d[mi][ni], ah[mi], bh[ni]);
                    mma_bf16(d[mi][ni], ah[mi], bl[ni]);
                    mma_bf16(d[mi][ni], al[mi], bh[ni]);
                }
        }
    }

    // epilogue: d0,d1 -> (row, col..col+1); d2,d3 -> (row+8, ...)
#pragma unroll
    for (int mi = 0; mi < 4; mi++) {
#pragma unroll
        for (int ni = 0; ni < 4; ni++) {
            int row = bm + wr*64 + mi*16 + (lane >> 2);
            int col = bn + wc*32 + ni*8 + (lane & 3)*2;
            float2* p0 = (float2*)&C[(size_t)row * J + col];
            float2* p1 = (float2*)&C[(size_t)(row + 8) * J + col];
            *p0 = make_float2(d[mi][ni][0], d[mi][ni][1]);
            *p1 = make_float2(d[mi][ni][2], d[mi][ni][3]);
        }
    }
}

// ---------------- interleaved RoPE, in place ----------------
__global__ void rope_kernel(float* __restrict__ buf,
                            const float* __restrict__ cosb,
                            const float* __restrict__ sinb, int nh)
{
    int idx = blockIdx.x * blockDim.x + threadIdx.x;
    int total = NR_ * nh * 16;
    if (idx >= total) return;
    int j    = idx & 15;
    int rest = idx >> 4;
    int head = rest % nh;
    int row  = rest / nh;
    int t    = row & (T_ - 1);
    float c = cosb[t*16 + j];
    float s = sinb[t*16 + j];
    float* p = buf + (size_t)row * (nh*32) + head*32 + 2*j;
    float x1 = p[0], x2 = p[1];
    p[0] = x1*c - x2*s;
    p[1] = x1*s + x2*c;
}

// ---------------- flash attention (4-member ensemble) + combine + RMS norm ----------------
__global__ __launch_bounds__(256) void attn_kernel(
    const float* __restrict__ q, const float* __restrict__ k, const float* __restrict__ v,
    const float* __restrict__ rawm, const float* __restrict__ wsc,
    const float* __restrict__ gamma, float* __restrict__ outn)
{
    extern __shared__ float smf[];
    float* Qs   = smf;             // 64*33
    float* Ks   = Qs + 64*33;      // 64*33
    float* Vs   = Ks + 64*33;      // 64*128
    float* Ps   = Vs + 64*128;     // 64*65
    float* m_s  = Ps + 64*65;      // 64
    float* l_s  = m_s + 64;        // 64
    float* al_s = l_s + 64;        // 64
    float* gma  = al_s + 64;       // 128

    const int tid  = threadIdx.x;
    const int tx   = tid & 15;
    const int ty   = tid >> 4;
    const int lane = tid & 31;
    const int warp = tid >> 5;
    const int qt   = (int)gridDim.x - 1 - (int)blockIdx.x;
    const int h    = blockIdx.y;
    const int b    = blockIdx.z;
    const int hkv  = h >> 2;
    const float scale = 0.17677669529663687f;

    if (tid < 128) gma[tid] = gamma[tid];
    const float ws0 = wsc[0];

    float comb[4][8];
#pragma unroll
    for (int i = 0; i < 4; i++)
#pragma unroll
        for (int j = 0; j < 8; j++) comb[i][j] = 0.f;

    const int rowbase = b*T_ + qt*64;

    for (int mm = 0; mm < 4; mm++) {
        __syncthreads();
        if (tid < 64) { m_s[tid] = -1e30f; l_s[tid] = 0.f; }
        {
#pragma unroll
            for (int u = 0; u < 2; u++) {
                int li = tid*2 + u;
                int r = li >> 3, seg = li & 7;
                const float* p = q + (size_t)(rowbase + r)*E_ + (h*4 + mm)*32 + seg*4;
                float4 qa = *(const float4*)p;
                float* dd = Qs + r*33 + seg*4;
                dd[0]=qa.x; dd[1]=qa.y; dd[2]=qa.z; dd[3]=qa.w;
            }
        }
        float acc[4][8];
#pragma unroll
        for (int i = 0; i < 4; i++)
#pragma unroll
            for (int j = 0; j < 8; j++) acc[i][j] = 0.f;

#pragma unroll 1
        for (int kt = 0; kt <= qt; kt++) {
            const int kbase = b*T_ + kt*64;
            float4 kr[2], vr[8];
#pragma unroll
            for (int u = 0; u < 2; u++) {
                int li = tid*2 + u;
                int r = li >> 3, seg = li & 7;
                kr[u] = *(const float4*)(k + (size_t)(kbase + r)*KVW_ + (hkv*4 + mm)*32 + seg*4);
            }
#pragma unroll
            for (int u = 0; u < 8; u++) {
                int li = u*256 + tid;
                int r = li >> 5, f4 = li & 31;
                vr[u] = *(const float4*)(v + (size_t)(kbase + r)*KVW_ + hkv*128 + f4*4);
            }
            __syncthreads();
#pragma unroll
            for (int u = 0; u < 2; u++) {
                int li = tid*2 + u;
                int r = li >> 3, seg = li & 7;
                float* dd = Ks + r*33 + seg*4;
                dd[0]=kr[u].x; dd[1]=kr[u].y; dd[2]=kr[u].z; dd[3]=kr[u].w;
            }
#pragma unroll
            for (int u = 0; u < 8; u++) {
                int li = u*256 + tid;
                *(float4*)(Vs + li*4) = vr[u];
            }
            __syncthreads();

            float s[4][4];
#pragma unroll
            for (int i = 0; i < 4; i++)
#pragma unroll
                for (int j = 0; j < 4; j++) s[i][j] = 0.f;
#pragma unroll 8
            for (int dd = 0; dd < 32; dd++) {
                float a[4], bb[4];
#pragma unroll
                for (int i = 0; i < 4; i++) a[i]  = Qs[(ty + 16*i)*33 + dd];
#pragma unroll
                for (int j = 0; j < 4; j++) bb[j] = Ks[(tx + 16*j)*33 + dd];
#pragma unroll
                for (int i = 0; i < 4; i++)
#pragma unroll
                    for (int j = 0; j < 4; j++) s[i][j] += a[i]*bb[j];
            }
#pragma unroll
            for (int i = 0; i < 4; i++) {
                int qi = qt*64 + ty + 16*i;
#pragma unroll
                for (int j = 0; j < 4; j++) {
                    int kj = kt*64 + tx + 16*j;
                    float sv = s[i][j]*scale;
                    if (kj > qi) sv = -1e30f;
                    s[i][j] = sv;
                    Ps[(ty + 16*i)*65 + tx + 16*j] = sv;
                }
            }
            __syncthreads();

#pragma unroll
            for (int q8 = 0; q8 < 8; q8++) {
                int r = warp*8 + q8;
                float vmax = fmaxf(Ps[r*65 + lane], Ps[r*65 + lane + 32]);
#pragma unroll
                for (int o = 16; o > 0; o >>= 1)
                    vmax = fmaxf(vmax, __shfl_xor_sync(0xffffffffu, vmax, o));
                if (lane == 0) {
                    float nm = fmaxf(m_s[r], vmax);
                    al_s[r] = __expf(m_s[r] - nm);
                    m_s[r] = nm;
                }
            }
            __syncthreads();

#pragma unroll
            for (int i = 0; i < 4; i++) {
                int r = ty + 16*i;
                float mv = m_s[r], al = al_s[r];
#pragma unroll
                for (int j = 0; j < 4; j++)
                    Ps[r*65 + tx + 16*j] = __expf(s[i][j] - mv);
#pragma unroll
                for (int j = 0; j < 8; j++) acc[i][j] *= al;
            }
            __syncthreads();

#pragma unroll
            for (int q8 = 0; q8 < 8; q8++) {
                int r = warp*8 + q8;
                float vs = Ps[r*65 + lane] + Ps[r*65 + lane + 32];
#pragma unroll
                for (int o = 16; o > 0; o >>= 1)
                    vs += __shfl_xor_sync(0xffffffffu, vs, o);
                if (lane == 0) l_s[r] = l_s[r]*al_s[r] + vs;
            }

#pragma unroll 4
            for (int kk = 0; kk < 64; kk++) {
                float pp[4];
#pragma unroll
                for (int i = 0; i < 4; i++) pp[i] = Ps[(ty + 16*i)*65 + kk];
                float4 v0 = *(const float4*)(Vs + kk*128 + tx*4);
                float4 v1 = *(const float4*)(Vs + kk*128 + 64 + tx*4);
                float vv[8] = {v0.x,v0.y,v0.z,v0.w,v1.x,v1.y,v1.z,v1.w};
#pragma unroll
                for (int i = 0; i < 4; i++)
#pragma unroll
                    for (int j = 0; j < 8; j++) acc[i][j] += pp[i]*vv[j];
            }
        } // kt

        __syncthreads();
        float wm = tanhf(rawm[mm]) * ws0;
#pragma unroll
        for (int i = 0; i < 4; i++) {
            float inv = wm / l_s[ty + 16*i];
#pragma unroll
            for (int j = 0; j < 8; j++) comb[i][j] += inv * acc[i][j];
        }
    } // member

#pragma unroll
    for (int i = 0; i < 4; i++) {
        float ps = 0.f;
#pragma unroll
        for (int j = 0; j < 8; j++) ps += comb[i][j]*comb[i][j];
        Ps[(ty + 16*i)*65 + tx] = ps;
    }
    __syncthreads();
    if (tid < 64) {
        float ssum = 0.f;
#pragma unroll
        for (int xx = 0; xx < 16; xx++) ssum += Ps[tid*65 + xx];
        m_s[tid] = rsqrtf(ssum*(1.0f/128.0f) + 1e-5f);
    }
    __syncthreads();
#pragma unroll
    for (int i = 0; i < 4; i++) {
        int r = ty + 16*i;
        float rs = m_s[r];
        float* op = outn + (size_t)(rowbase + r)*E_ + h*128;
        float4 o0, o1;
        o0.x = comb[i][0]*rs*gma[tx*4+0];
        o0.y = comb[i][1]*rs*gma[tx*4+1];
        o0.z = comb[i][2]*rs*gma[tx*4+2];
        o0.w = comb[i][3]*rs*gma[tx*4+3];
        o1.x = comb[i][4]*rs*gma[64+tx*4+0];
        o1.y = comb[i][5]*rs*gma[64+tx*4+1];
        o1.z = comb[i][6]*rs*gma[64+tx*4+2];
        o1.w = comb[i][7]*rs*gma[64+tx*4+3];
        *(float4*)(op + tx*4)      = o0;
        *(float4*)(op + 64 + tx*4) = o1;
    }
}

// ---------------- launch ----------------
extern "C" void kernel_launch(void* const* d_in, const int* in_sizes, int n_in,
                              void* d_out, int out_size)
{
    const float* x     = (const float*)d_in[0];
    const float* cosb  = (const float*)d_in[1];
    const float* sinb  = (const float*)d_in[2];
    const float* q_w   = (const float*)d_in[3];
    const float* k_w   = (const float*)d_in[4];
    const float* v_w   = (const float*)d_in[5];
    const float* out_w = (const float*)d_in[6];
    const float* rawm  = (const float*)d_in[7];
    const float* wsc   = (const float*)d_in[8];
    const float* gamma = (const float*)d_in[9];
    float* out = (float*)d_out;

    float *gq, *gk, *gv, *gn;
    cudaGetSymbolAddress((void**)&gq, g_q);
    cudaGetSymbolAddress((void**)&gk, g_k);
    cudaGetSymbolAddress((void**)&gv, g_v);
    cudaGetSymbolAddress((void**)&gn, g_n);
    __nv_bfloat16 *ah, *al, *qwh, *qwl, *kwh, *kwl, *vwh, *vwl, *owh, *owl;
    cudaGetSymbolAddress((void**)&ah,  g_ah);
    cudaGetSymbolAddress((void**)&al,  g_al);
    cudaGetSymbolAddress((void**)&qwh, g_qwh);
    cudaGetSymbolAddress((void**)&qwl, g_qwl);
    cudaGetSymbolAddress((void**)&kwh, g_kwh);
    cudaGetSymbolAddress((void**)&kwl, g_kwl);
    cudaGetSymbolAddress((void**)&vwh, g_vwh);
    cudaGetSymbolAddress((void**)&vwl, g_vwl);
    cudaGetSymbolAddress((void**)&owh, g_owh);
    cudaGetSymbolAddress((void**)&owl, g_owl);

    const int attn_smem = (64*33*2 + 64*128 + 64*65 + 64*3 + 128) * sizeof(float); // 67584
    cudaFuncSetAttribute(attn_kernel, cudaFuncAttributeMaxDynamicSharedMemorySize, attn_smem);

    // split conversions (fp32 -> bf16 hi/lo)
    {
        int n4;
        n4 = NR_*E_/4;   cvt_split<<<(n4+255)/256, 256>>>((const float4*)x,     (__nv_bfloat162*)ah,  (__nv_bfloat162*)al,  n4);
        n4 = E_*E_/4;    cvt_split<<<(n4+255)/256, 256>>>((const float4*)q_w,   (__nv_bfloat162*)qwh, (__nv_bfloat162*)qwl, n4);
        n4 = KVW_*E_/4;  cvt_split<<<(n4+255)/256, 256>>>((const float4*)k_w,   (__nv_bfloat162*)kwh, (__nv_bfloat162*)kwl, n4);
        n4 = KVW_*E_/4;  cvt_split<<<(n4+255)/256, 256>>>((const float4*)v_w,   (__nv_bfloat162*)vwh, (__nv_bfloat162*)vwl, n4);
        n4 = E_*E_/4;    cvt_split<<<(n4+255)/256, 256>>>((const float4*)out_w, (__nv_bfloat162*)owh, (__nv_bfloat162*)owl, n4);
    }

    // projections (HMMA bf16, split x3)
    mma_gemm<<<dim3(E_/128,   NR_/128), 256>>>(ah, al, qwh, qwl, gq, E_,   E_);
    mma_gemm<<<dim3(KVW_/128, NR_/128), 256>>>(ah, al, kwh, kwl, gk, KVW_, E_);
    mma_gemm<<<dim3(KVW_/128, NR_/128), 256>>>(ah, al, vwh, vwl, gv, KVW_, E_);

    // RoPE
    rope_kernel<<<(NR_*64*16)/256, 256>>>(gq, cosb, sinb, 64);
    rope_kernel<<<(NR_*16*16)/256, 256>>>(gk, cosb, sinb, 16);

    // attention + combine + RMS norm
    attn_kernel<<<dim3(T_/64, H_, B_), 256, attn_smem>>>(gq, gk, gv, rawm, wsc, gamma, gn);

    // out projection: split the normed activations, then HMMA GEMM
    {
        int n4 = NR_*E_/4;
        cvt_split<<<(n4+255)/256, 256>>>((const float4*)gn, (__nv_bfloat162*)ah, (__nv_bfloat162*)al, n4);
    }
    mma_gemm<<<dim3(E_/128, NR_/128), 256>>>(ah, al, owh, owl, out, E_, E_);
}

// round 5
// speedup vs baseline: 2.7816x; 2.1823x over previous
#include <cuda_runtime.h>
#include <cuda_bf16.h>
#include <math.h>
#include <stdint.h>

#define B_   2
#define T_   2048
#define E_   2048
#define H_   16
#define KVW_ 512
#define NR_  (B_*T_)   // 4096 rows

// ---------------- scratch (static device globals; no allocation) ----------------
__device__ __align__(16) float g_q[(size_t)NR_ * E_];
__device__ __align__(16) float g_k[(size_t)NR_ * KVW_];
__device__ __align__(16) float g_v[(size_t)NR_ * KVW_];
__device__ __align__(16) float g_part[4][(size_t)NR_ * E_];   // per-member w*O/l
// bf16 split buffers
__device__ __align__(16) __nv_bfloat16 g_ah[(size_t)NR_ * E_];   // x, later normed
__device__ __align__(16) __nv_bfloat16 g_al[(size_t)NR_ * E_];
__device__ __align__(16) __nv_bfloat16 g_qwh[(size_t)E_ * E_];
__device__ __align__(16) __nv_bfloat16 g_qwl[(size_t)E_ * E_];
__device__ __align__(16) __nv_bfloat16 g_kwh[(size_t)KVW_ * E_];
__device__ __align__(16) __nv_bfloat16 g_kwl[(size_t)KVW_ * E_];
__device__ __align__(16) __nv_bfloat16 g_vwh[(size_t)KVW_ * E_];
__device__ __align__(16) __nv_bfloat16 g_vwl[(size_t)KVW_ * E_];
__device__ __align__(16) __nv_bfloat16 g_owh[(size_t)E_ * E_];
__device__ __align__(16) __nv_bfloat16 g_owl[(size_t)E_ * E_];

__device__ __forceinline__ uint32_t smem_u32(const void* p) {
    uint32_t a;
    asm("{ .reg .u64 t; cvta.to.shared.u64 t, %1; cvt.u32.u64 %0, t; }" : "=r"(a) : "l"(p));
    return a;
}
__device__ __forceinline__ void ldsm_x4(uint32_t* r, uint32_t addr) {
    asm volatile("ldmatrix.sync.aligned.m8n8.x4.shared.b16 {%0,%1,%2,%3}, [%4];"
        : "=r"(r[0]), "=r"(r[1]), "=r"(r[2]), "=r"(r[3]) : "r"(addr));
}
__device__ __forceinline__ void ldsm_x4t(uint32_t* r, uint32_t addr) {
    asm volatile("ldmatrix.sync.aligned.m8n8.x4.trans.shared.b16 {%0,%1,%2,%3}, [%4];"
        : "=r"(r[0]), "=r"(r[1]), "=r"(r[2]), "=r"(r[3]) : "r"(addr));
}
__device__ __forceinline__ void ldsm_x2(uint32_t* r, uint32_t addr) {
    asm volatile("ldmatrix.sync.aligned.m8n8.x2.shared.b16 {%0,%1}, [%2];"
        : "=r"(r[0]), "=r"(r[1]) : "r"(addr));
}
__device__ __forceinline__ void mma_bf16(float* d, const uint32_t* a, const uint32_t* b) {
    asm volatile("mma.sync.aligned.m16n8k16.row.col.f32.bf16.bf16.f32 "
        "{%0,%1,%2,%3}, {%4,%5,%6,%7}, {%8,%9}, {%0,%1,%2,%3};"
        : "+f"(d[0]), "+f"(d[1]), "+f"(d[2]), "+f"(d[3])
        : "r"(a[0]), "r"(a[1]), "r"(a[2]), "r"(a[3]), "r"(b[0]), "r"(b[1]));
}
__device__ __forceinline__ void split_bf16(float v, __nv_bfloat16& h, __nv_bfloat16& l) {
    h = __float2bfloat16(v);
    l = __float2bfloat16(v - __bfloat162float(h));
}

// ---------------- fp32 -> (bf16 hi, bf16 lo) split ----------------
__global__ void cvt_split(const float4* __restrict__ in,
                          __nv_bfloat162* __restrict__ hi,
                          __nv_bfloat162* __restrict__ lo, int n4)
{
    int i = blockIdx.x * blockDim.x + threadIdx.x;
    if (i >= n4) return;
    float4 v = in[i];
    __nv_bfloat16 h0,h1,h2,h3,l0,l1,l2,l3;
    split_bf16(v.x,h0,l0); split_bf16(v.y,h1,l1);
    split_bf16(v.z,h2,l2); split_bf16(v.w,h3,l3);
    hi[i*2]   = __halves2bfloat162(h0, h1);
    hi[i*2+1] = __halves2bfloat162(h2, h3);
    lo[i*2]   = __halves2bfloat162(l0, l1);
    lo[i*2+1] = __halves2bfloat162(l2, l3);
}

// ---------------- HMMA GEMM: C[N,J] = A[N,K] @ W[J,K]^T, split-bf16 x3 ----------------
#define TSTRIDE 40
__global__ __launch_bounds__(256) void mma_gemm(
    const __nv_bfloat16* __restrict__ Ah, const __nv_bfloat16* __restrict__ Al,
    const __nv_bfloat16* __restrict__ Bh, const __nv_bfloat16* __restrict__ Bl,
    float* __restrict__ C, int J, int K)
{
    __shared__ __align__(16) __nv_bfloat16 sm[4][128 * TSTRIDE];

    const int tid  = threadIdx.x;
    const int lane = tid & 31;
    const int warp = tid >> 5;
    const int wr   = warp >> 2;
    const int wc   = warp & 3;
    const int bm   = blockIdx.y * 128;
    const int bn   = blockIdx.x * 128;

    const uint32_t sA_h = smem_u32(sm[0]);
    const uint32_t sA_l = smem_u32(sm[1]);
    const uint32_t sB_h = smem_u32(sm[2]);
    const uint32_t sB_l = smem_u32(sm[3]);

    const int K8 = K >> 3;
    const uint4* pAh = (const uint4*)Ah;
    const uint4* pAl = (const uint4*)Al;
    const uint4* pBh = (const uint4*)Bh;
    const uint4* pBl = (const uint4*)Bl;

    float d[4][4][4];
#pragma unroll
    for (int mi = 0; mi < 4; mi++)
#pragma unroll
        for (int ni = 0; ni < 4; ni++)
#pragma unroll
            for (int e = 0; e < 4; e++) d[mi][ni][e] = 0.f;

    const int a_row = lane & 15, a_coff = (lane >> 4) * 8;
    const int b_row = lane & 7,  b_coff = ((lane >> 3) & 1) * 8;

    const int nit = K >> 5;
#pragma unroll 1
    for (int it = 0; it < nit; it++) {
        const int k0u4 = it * 4;
        __syncthreads();
#pragma unroll
        for (int u = 0; u < 2; u++) {
            int c   = u * 256 + tid;
            int row = c >> 2, ch = c & 3;
            size_t ga = (size_t)(bm + row) * K8 + k0u4 + ch;
            size_t gb = (size_t)(bn + row) * K8 + k0u4 + ch;
            *(uint4*)((char*)sm[0] + row * (TSTRIDE*2) + ch * 16) = pAh[ga];
            *(uint4*)((char*)sm[1] + row * (TSTRIDE*2) + ch * 16) = pAl[ga];
            *(uint4*)((char*)sm[2] + row * (TSTRIDE*2) + ch * 16) = pBh[gb];
            *(uint4*)((char*)sm[3] + row * (TSTRIDE*2) + ch * 16) = pBl[gb];
        }
        __syncthreads();

#pragma unroll
        for (int kk = 0; kk < 32; kk += 16) {
            uint32_t ah[4][4], al[4][4], bh[4][2], bl[4][2];
#pragma unroll
            for (int mi = 0; mi < 4; mi++) {
                int row = wr*64 + mi*16 + a_row;
                uint32_t off = (uint32_t)(row * (TSTRIDE*2) + (kk + a_coff) * 2);
                ldsm_x4(ah[mi], sA_h + off);
                ldsm_x4(al[mi], sA_l + off);
            }
#pragma unroll
            for (int ni = 0; ni < 4; ni++) {
                int row = wc*32 + ni*8 + b_row;
                uint32_t off = (uint32_t)(row * (TSTRIDE*2) + (kk + b_coff) * 2);
                ldsm_x2(bh[ni], sB_h + off);
                ldsm_x2(bl[ni], sB_l + off);
            }
#pragma unroll
            for (int mi = 0; mi < 4; mi++)
#pragma unroll
                for (int ni = 0; ni < 4; ni++) {
                    mma_bf16(d[mi][ni], ah[mi], bh[ni]);
                    mma_bf16(d[mi][ni], ah[mi], bl[ni]);
                    mma_bf16(d[mi][ni], al[mi], bh[ni]);
                }
        }
    }

#pragma unroll
    for (int mi = 0; mi < 4; mi++) {
#pragma unroll
        for (int ni = 0; ni < 4; ni++) {
            int row = bm + wr*64 + mi*16 + (lane >> 2);
            int col = bn + wc*32 + ni*8 + (lane & 3)*2;
            *(float2*)&C[(size_t)row * J + col]       = make_float2(d[mi][ni][0], d[mi][ni][1]);
            *(float2*)&C[(size_t)(row + 8) * J + col] = make_float2(d[mi][ni][2], d[mi][ni][3]);
        }
    }
}

// ---------------- interleaved RoPE, in place ----------------
__global__ void rope_kernel(float* __restrict__ buf,
                            const float* __restrict__ cosb,
                            const float* __restrict__ sinb, int nh)
{
    int idx = blockIdx.x * blockDim.x + threadIdx.x;
    int total = NR_ * nh * 16;
    if (idx >= total) return;
    int j    = idx & 15;
    int rest = idx >> 4;
    int head = rest % nh;
    int row  = rest / nh;
    int t    = row & (T_ - 1);
    float c = cosb[t*16 + j];
    float s = sinb[t*16 + j];
    float* p = buf + (size_t)row * (nh*32) + head*32 + 2*j;
    float x1 = p[0], x2 = p[1];
    p[0] = x1*c - x2*s;
    p[1] = x1*s + x2*c;
}

// ---------------- HMMA flash attention: one (q-tile, head, batch, member) per CTA ----------------
// smem layout (bytes): QH 0, QL 5120, KH 10240, KL 15360, VH 20480, VL 37888,
//                      PH 55296, PL 64512, stats 73728..75520
#define QS 40
#define VS 136
#define PS 72
#define ATTN_SMEM 75520
__global__ __launch_bounds__(256) void attn_mma(
    const float* __restrict__ q, const float* __restrict__ k, const float* __restrict__ v,
    const float* __restrict__ rawm, const float* __restrict__ wsc,
    float* __restrict__ part)
{
    extern __shared__ char sm[];
    __nv_bfloat16* QH = (__nv_bfloat16*)(sm);
    __nv_bfloat16* QL = (__nv_bfloat16*)(sm + 5120);
    __nv_bfloat16* KH = (__nv_bfloat16*)(sm + 10240);
    __nv_bfloat16* KL = (__nv_bfloat16*)(sm + 15360);
    __nv_bfloat16* VH = (__nv_bfloat16*)(sm + 20480);
    __nv_bfloat16* VL = (__nv_bfloat16*)(sm + 37888);
    __nv_bfloat16* PH = (__nv_bfloat16*)(sm + 55296);
    __nv_bfloat16* PL = (__nv_bfloat16*)(sm + 64512);
    float* m_s  = (float*)(sm + 73728);
    float* l_s  = (float*)(sm + 73728 + 256);
    float* al_s = (float*)(sm + 73728 + 512);
    float* pmax = (float*)(sm + 73728 + 768);   // [2][64]
    float* psum = (float*)(sm + 73728 + 1280);  // [2][64]

    const int tid    = threadIdx.x;
    const int lane   = tid & 31;
    const int warp   = tid >> 5;
    const int rs     = (warp & 3) * 16;   // row strip (0,16,32,48)
    const int cstrip = warp >> 2;         // 0/1
    const int qt  = (int)gridDim.x - 1 - (int)blockIdx.x;
    const int h   = blockIdx.y;
    const int bz  = blockIdx.z;
    const int b   = bz >> 2, mm = bz & 3;
    const int hkv = h >> 2;
    const float scale = 0.17677669529663687f;
    const int rowbase = b*T_ + qt*64;

    const uint32_t qh_b = smem_u32(QH), ql_b = smem_u32(QL);
    const uint32_t kh_b = smem_u32(KH), kl_b = smem_u32(KL);
    const uint32_t vh_b = smem_u32(VH), vl_b = smem_u32(VL);
    const uint32_t ph_b = smem_u32(PH), pl_b = smem_u32(PL);

    // load Q (scale folded), split to bf16 hi/lo
#pragma unroll
    for (int u = 0; u < 2; u++) {
        int li = tid*2 + u;
        int r = li >> 3, seg = li & 7;
        float4 qa = *(const float4*)(q + (size_t)(rowbase + r)*E_ + (h*4 + mm)*32 + seg*4);
        qa.x *= scale; qa.y *= scale; qa.z *= scale; qa.w *= scale;
        __nv_bfloat16 hh, ll;
        int base = r*QS + seg*4;
        split_bf16(qa.x, hh, ll); QH[base+0]=hh; QL[base+0]=ll;
        split_bf16(qa.y, hh, ll); QH[base+1]=hh; QL[base+1]=ll;
        split_bf16(qa.z, hh, ll); QH[base+2]=hh; QL[base+2]=ll;
        split_bf16(qa.w, hh, ll); QH[base+3]=hh; QL[base+3]=ll;
    }
    if (tid < 64) { m_s[tid] = -1e30f; l_s[tid] = 0.f; }

    float o[8][4];
#pragma unroll
    for (int n8 = 0; n8 < 8; n8++)
#pragma unroll
        for (int e = 0; e < 4; e++) o[n8][e] = 0.f;

    const int r0 = rs + (lane >> 2);
    const int r1 = r0 + 8;

#pragma unroll 1
    for (int kt = 0; kt <= qt; kt++) {
        const int kbase = b*T_ + kt*64;
        // stage global loads
        float4 kr[2], vr[8];
#pragma unroll
        for (int u = 0; u < 2; u++) {
            int li = tid*2 + u;
            int r = li >> 3, seg = li & 7;
            kr[u] = *(const float4*)(k + (size_t)(kbase + r)*KVW_ + (hkv*4 + mm)*32 + seg*4);
        }
#pragma unroll
        for (int u = 0; u < 8; u++) {
            int li = u*256 + tid;
            int kv = li >> 5, e4 = li & 31;
            vr[u] = *(const float4*)(v + (size_t)(kbase + kv)*KVW_ + hkv*128 + e4*4);
        }
        __syncthreads();   // prior MMA reads of K/V/P smem complete
        // store K hi/lo
#pragma unroll
        for (int u = 0; u < 2; u++) {
            int li = tid*2 + u;
            int r = li >> 3, seg = li & 7;
            int base = r*QS + seg*4;
            __nv_bfloat16 hh, ll;
            split_bf16(kr[u].x, hh, ll); KH[base+0]=hh; KL[base+0]=ll;
            split_bf16(kr[u].y, hh, ll); KH[base+1]=hh; KL[base+1]=ll;
            split_bf16(kr[u].z, hh, ll); KH[base+2]=hh; KL[base+2]=ll;
            split_bf16(kr[u].w, hh, ll); KH[base+3]=hh; KL[base+3]=ll;
        }
        // store V hi/lo [kv][e] (row-major, for trans ldmatrix)
#pragma unroll
        for (int u = 0; u < 8; u++) {
            int li = u*256 + tid;
            int kv = li >> 5, e4 = li & 31;
            int base = kv*VS + e4*4;
            __nv_bfloat16 hh, ll;
            split_bf16(vr[u].x, hh, ll); VH[base+0]=hh; VL[base+0]=ll;
            split_bf16(vr[u].y, hh, ll); VH[base+1]=hh; VL[base+1]=ll;
            split_bf16(vr[u].z, hh, ll); VH[base+2]=hh; VL[base+2]=ll;
            split_bf16(vr[u].w, hh, ll); VH[base+3]=hh; VL[base+3]=ll;
        }
        __syncthreads();

        // S = Q K^T (64x64), warp tile 16x32 at (rs, cstrip*32)
        float s[4][4];
#pragma unroll
        for (int n8 = 0; n8 < 4; n8++)
#pragma unroll
            for (int e = 0; e < 4; e++) s[n8][e] = 0.f;
#pragma unroll
        for (int ks = 0; ks < 2; ks++) {
            int kk = ks*16;
            uint32_t aH[4], aL[4];
            uint32_t aoff = (uint32_t)(((rs + (lane & 15))*QS + kk + (lane >> 4)*8) * 2);
            ldsm_x4(aH, qh_b + aoff);
            ldsm_x4(aL, ql_b + aoff);
            uint32_t bH[2][4], bL[2][4];
#pragma unroll
            for (int np = 0; np < 2; np++) {
                int nrow = cstrip*32 + np*16 + (lane & 7) + 8*(lane >> 4);
                uint32_t boff = (uint32_t)((nrow*QS + kk + 8*((lane >> 3) & 1)) * 2);
                ldsm_x4(bH[np], kh_b + boff);
                ldsm_x4(bL[np], kl_b + boff);
            }
#pragma unroll
            for (int n8 = 0; n8 < 4; n8++) {
                uint32_t* bh = &bH[n8 >> 1][(n8 & 1)*2];
                uint32_t* bl = &bL[n8 >> 1][(n8 & 1)*2];
                mma_bf16(s[n8], aH, bh);
                mma_bf16(s[n8], aH, bl);
                mma_bf16(s[n8], aL, bh);
            }
        }
        // causal mask (diagonal tile only)
        if (kt == qt) {
#pragma unroll
            for (int n8 = 0; n8 < 4; n8++) {
                int c0 = cstrip*32 + n8*8 + (lane & 3)*2;
                if (c0     > r0) s[n8][0] = -1e30f;
                if (c0 + 1 > r0) s[n8][1] = -1e30f;
                if (c0     > r1) s[n8][2] = -1e30f;
                if (c0 + 1 > r1) s[n8][3] = -1e30f;
            }
        }
        // row max partials
        {
            float mx0 = s[0][0], mx1 = s[0][2];
#pragma unroll
            for (int n8 = 0; n8 < 4; n8++) {
                mx0 = fmaxf(mx0, fmaxf(s[n8][0], s[n8][1]));
                mx1 = fmaxf(mx1, fmaxf(s[n8][2], s[n8][3]));
            }
            mx0 = fmaxf(mx0, __shfl_xor_sync(0xffffffffu, mx0, 1));
            mx0 = fmaxf(mx0, __shfl_xor_sync(0xffffffffu, mx0, 2));
            mx1 = fmaxf(mx1, __shfl_xor_sync(0xffffffffu, mx1, 1));
            mx1 = fmaxf(mx1, __shfl_xor_sync(0xffffffffu, mx1, 2));
            if ((lane & 3) == 0) {
                pmax[cstrip*64 + r0] = mx0;
                pmax[cstrip*64 + r1] = mx1;
            }
        }
        __syncthreads();
        if (tid < 64) {
            float vm = fmaxf(pmax[tid], pmax[64 + tid]);
            float nm = fmaxf(m_s[tid], vm);
            al_s[tid] = __expf(m_s[tid] - nm);
            m_s[tid] = nm;
        }
        __syncthreads();
        // p = exp(s - m), store hi/lo, row sums, O rescale
        {
            float mv0 = m_s[r0], mv1 = m_s[r1];
            float a0 = al_s[r0], a1 = al_s[r1];
            float sum0 = 0.f, sum1 = 0.f;
#pragma unroll
            for (int n8 = 0; n8 < 4; n8++) {
                float p00 = __expf(s[n8][0] - mv0);
                float p01 = __expf(s[n8][1] - mv0);
                float p10 = __expf(s[n8][2] - mv1);
                float p11 = __expf(s[n8][3] - mv1);
                sum0 += p00 + p01;
                sum1 += p10 + p11;
                int c0 = cstrip*32 + n8*8 + (lane & 3)*2;
                __nv_bfloat16 h00,l00,h01,l01,h10,l10,h11,l11;
                split_bf16(p00,h00,l00); split_bf16(p01,h01,l01);
                split_bf16(p10,h10,l10); split_bf16(p11,h11,l11);
                *(__nv_bfloat162*)&PH[r0*PS + c0] = __halves2bfloat162(h00, h01);
                *(__nv_bfloat162*)&PL[r0*PS + c0] = __halves2bfloat162(l00, l01);
                *(__nv_bfloat162*)&PH[r1*PS + c0] = __halves2bfloat162(h10, h11);
                *(__nv_bfloat162*)&PL[r1*PS + c0] = __halves2bfloat162(l10, l11);
            }
            sum0 += __shfl_xor_sync(0xffffffffu, sum0, 1);
            sum0 += __shfl_xor_sync(0xffffffffu, sum0, 2);
            sum1 += __shfl_xor_sync(0xffffffffu, sum1, 1);
            sum1 += __shfl_xor_sync(0xffffffffu, sum1, 2);
            if ((lane & 3) == 0) {
                psum[cstrip*64 + r0] = sum0;
                psum[cstrip*64 + r1] = sum1;
            }
#pragma unroll
            for (int n8 = 0; n8 < 8; n8++) {
                o[n8][0] *= a0; o[n8][1] *= a0;
                o[n8][2] *= a1; o[n8][3] *= a1;
            }
        }
        __syncthreads();
        if (tid < 64) l_s[tid] = l_s[tid]*al_s[tid] + psum[tid] + psum[64 + tid];

        // O += P V  (warp tile 16 rows x 64 cols at col base cstrip*64)
#pragma unroll
        for (int ks = 0; ks < 4; ks++) {
            int kk = ks*16;
            uint32_t pHf[4], pLf[4];
            uint32_t poff = (uint32_t)(((rs + (lane & 15))*PS + kk + (lane >> 4)*8) * 2);
            ldsm_x4(pHf, ph_b + poff);
            ldsm_x4(pLf, pl_b + poff);
#pragma unroll
            for (int np = 0; np < 4; np++) {
                int n0 = cstrip*64 + np*16;
                int vrow = kk + (lane & 7) + 8*((lane >> 3) & 1);
                uint32_t voff = (uint32_t)((vrow*VS + n0 + 8*(lane >> 4)) * 2);
                uint32_t vHf[4], vLf[4];
                ldsm_x4t(vHf, vh_b + voff);
                ldsm_x4t(vLf, vl_b + voff);
                mma_bf16(o[np*2],     pHf, &vHf[0]);
                mma_bf16(o[np*2],     pHf, &vLf[0]);
                mma_bf16(o[np*2],     pLf, &vHf[0]);
                mma_bf16(o[np*2 + 1], pHf, &vHf[2]);
                mma_bf16(o[np*2 + 1], pHf, &vLf[2]);
                mma_bf16(o[np*2 + 1], pLf, &vHf[2]);
            }
        }
    } // kt

    __syncthreads();
    const float wm = tanhf(rawm[mm]) * wsc[0];
    const float inv0 = wm / l_s[r0];
    const float inv1 = wm / l_s[r1];
    float* dst = part + (size_t)mm * ((size_t)NR_ * E_);
#pragma unroll
    for (int n8 = 0; n8 < 8; n8++) {
        int col = cstrip*64 + n8*8 + (lane & 3)*2;
        *(float2*)&dst[(size_t)(rowbase + r0)*E_ + h*128 + col] =
            make_float2(o[n8][0]*inv0, o[n8][1]*inv0);
        *(float2*)&dst[(size_t)(rowbase + r1)*E_ + h*128 + col] =
            make_float2(o[n8][2]*inv1, o[n8][3]*inv1);
    }
}

// ---------------- combine 4 members + RMS norm + gamma -> bf16 hi/lo ----------------
__global__ __launch_bounds__(256) void combine_kernel(
    const float* __restrict__ part, const float* __restrict__ gamma,
    __nv_bfloat16* __restrict__ hi, __nv_bfloat16* __restrict__ lo)
{
    const int tid = threadIdx.x, lane = tid & 31, w = tid >> 5;
    const int gid = blockIdx.x * 8 + w;          // row*16 + h
    const int row = gid >> 4, h = gid & 15;
    const size_t base = (size_t)row * E_ + h*128 + lane*4;
    float4 c = make_float4(0.f, 0.f, 0.f, 0.f);
#pragma unroll
    for (int m = 0; m < 4; m++) {
        float4 p = *(const float4*)&part[(size_t)m * ((size_t)NR_ * E_) + base];
        c.x += p.x; c.y += p.y; c.z += p.z; c.w += p.w;
    }
    float ss = c.x*c.x + c.y*c.y + c.z*c.z + c.w*c.w;
#pragma unroll
    for (int off = 16; off > 0; off >>= 1)
        ss += __shfl_xor_sync(0xffffffffu, ss, off);
    const float rsc = rsqrtf(ss * (1.0f/128.0f) + 1e-5f);
    const float4 g = *(const float4*)&gamma[lane*4];
    float v0 = c.x*rsc*g.x, v1 = c.y*rsc*g.y, v2 = c.z*rsc*g.z, v3 = c.w*rsc*g.w;
    __nv_bfloat16 h0,l0,h1,l1,h2,l2,h3,l3;
    split_bf16(v0,h0,l0); split_bf16(v1,h1,l1);
    split_bf16(v2,h2,l2); split_bf16(v3,h3,l3);
    *(__nv_bfloat162*)&hi[base]   = __halves2bfloat162(h0, h1);
    *(__nv_bfloat162*)&hi[base+2] = __halves2bfloat162(h2, h3);
    *(__nv_bfloat162*)&lo[base]   = __halves2bfloat162(l0, l1);
    *(__nv_bfloat162*)&lo[base+2] = __halves2bfloat162(l2, l3);
}

// ---------------- launch ----------------
extern "C" void kernel_launch(void* const* d_in, const int* in_sizes, int n_in,
                              void* d_out, int out_size)
{
    const float* x     = (const float*)d_in[0];
    const float* cosb  = (const float*)d_in[1];
    const float* sinb  = (const float*)d_in[2];
    const float* q_w   = (const float*)d_in[3];
    const float* k_w   = (const float*)d_in[4];
    const float* v_w   = (const float*)d_in[5];
    const float* out_w = (const float*)d_in[6];
    const float* rawm  = (const float*)d_in[7];
    const float* wsc   = (const float*)d_in[8];
    const float* gamma = (const float*)d_in[9];
    float* out = (float*)d_out;

    float *gq, *gk, *gv, *gpart;
    cudaGetSymbolAddress((void**)&gq, g_q);
    cudaGetSymbolAddress((void**)&gk, g_k);
    cudaGetSymbolAddress((void**)&gv, g_v);
    cudaGetSymbolAddress((void**)&gpart, g_part);
    __nv_bfloat16 *ah, *al, *qwh, *qwl, *kwh, *kwl, *vwh, *vwl, *owh, *owl;
    cudaGetSymbolAddress((void**)&ah,  g_ah);
    cudaGetSymbolAddress((void**)&al,  g_al);
    cudaGetSymbolAddress((void**)&qwh, g_qwh);
    cudaGetSymbolAddress((void**)&qwl, g_qwl);
    cudaGetSymbolAddress((void**)&kwh, g_kwh);
    cudaGetSymbolAddress((void**)&kwl, g_kwl);
    cudaGetSymbolAddress((void**)&vwh, g_vwh);
    cudaGetSymbolAddress((void**)&vwl, g_vwl);
    cudaGetSymbolAddress((void**)&owh, g_owh);
    cudaGetSymbolAddress((void**)&owl, g_owl);

    cudaFuncSetAttribute(attn_mma, cudaFuncAttributeMaxDynamicSharedMemorySize, ATTN_SMEM);

    // split conversions (fp32 -> bf16 hi/lo)
    {
        int n4;
        n4 = NR_*E_/4;   cvt_split<<<(n4+255)/256, 256>>>((const float4*)x,     (__nv_bfloat162*)ah,  (__nv_bfloat162*)al,  n4);
        n4 = E_*E_/4;    cvt_split<<<(n4+255)/256, 256>>>((const float4*)q_w,   (__nv_bfloat162*)qwh, (__nv_bfloat162*)qwl, n4);
        n4 = KVW_*E_/4;  cvt_split<<<(n4+255)/256, 256>>>((const float4*)k_w,   (__nv_bfloat162*)kwh, (__nv_bfloat162*)kwl, n4);
        n4 = KVW_*E_/4;  cvt_split<<<(n4+255)/256, 256>>>((const float4*)v_w,   (__nv_bfloat162*)vwh, (__nv_bfloat162*)vwl, n4);
        n4 = E_*E_/4;    cvt_split<<<(n4+255)/256, 256>>>((const float4*)out_w, (__nv_bfloat162*)owh, (__nv_bfloat162*)owl, n4);
    }

    // projections (HMMA bf16, split x3)
    mma_gemm<<<dim3(E_/128,   NR_/128), 256>>>(ah, al, qwh, qwl, gq, E_,   E_);
    mma_gemm<<<dim3(KVW_/128, NR_/128), 256>>>(ah, al, kwh, kwl, gk, KVW_, E_);
    mma_gemm<<<dim3(KVW_/128, NR_/128), 256>>>(ah, al, vwh, vwl, gv, KVW_, E_);

    // RoPE
    rope_kernel<<<(NR_*64*16)/256, 256>>>(gq, cosb, sinb, 64);
    rope_kernel<<<(NR_*16*16)/256, 256>>>(gk, cosb, sinb, 16);

    // attention (tensor core), one member per CTA
    attn_mma<<<dim3(T_/64, H_, B_*4), 256, ATTN_SMEM>>>(gq, gk, gv, rawm, wsc, gpart);

    // combine + RMS norm + gamma -> bf16 split
    combine_kernel<<<NR_*16/8, 256>>>(gpart, gamma, ah, al);

    // out projection
    mma_gemm<<<dim3(E_/128, NR_/128), 256>>>(ah, al, owh, owl, out, E_, E_);
}